// round 14
// baseline (speedup 1.0000x reference)
#include <cuda_runtime.h>
#include <cuda_bf16.h>
#include <cstdint>

#define BATCH 256
#define SEQT  256
#define HID   1024
#define G4H   4096
#define EMB   10
#define NVOC  10
#define NCLS  10

#define STG        49152                 // stage: Ahi 8K | Alo 8K | Bhi 16K | Blo 16K
#define SMEM_TOTAL (3 * STG)

// Device-global scratch (allocation-free rule)
__device__ __nv_bfloat16 g_Whi[G4H * HID];        // 8 MB  interleaved W hi
__device__ __nv_bfloat16 g_Wlo[G4H * HID];        // 8 MB  interleaved W lo
__device__ __nv_bfloat16 g_hA[2][BATCH * HID];    // h hi, double-buffered
__device__ __nv_bfloat16 g_hB[2][BATCH * HID];    // h lo
__device__ float g_c[BATCH * HID];
__device__ float g_xt[NVOC * G4H];
__device__ int   g_xflag;

// ------------------------- PTX helpers (baseline sm_80+ features) ----------
__device__ __forceinline__ uint32_t smem_u32(const void* p) {
    uint32_t a;
    asm("{ .reg .u64 t; cvta.to.shared.u64 t, %1; cvt.u32.u64 %0, t; }" : "=r"(a) : "l"(p));
    return a;
}
__device__ __forceinline__ void cp16(uint32_t dst, const void* src) {
    asm volatile("cp.async.cg.shared.global [%0], [%1], 16;" :: "r"(dst), "l"(src) : "memory");
}
#define CP_COMMIT() asm volatile("cp.async.commit_group;" ::: "memory")
#define CP_WAIT1()  asm volatile("cp.async.wait_group 1;" ::: "memory")
#define CP_WAIT0()  asm volatile("cp.async.wait_group 0;" ::: "memory")

__device__ __forceinline__ void ldsm4(uint32_t* r, uint32_t addr) {
    asm volatile("ldmatrix.sync.aligned.m8n8.x4.shared.b16 {%0,%1,%2,%3}, [%4];"
        : "=r"(r[0]), "=r"(r[1]), "=r"(r[2]), "=r"(r[3]) : "r"(addr));
}
__device__ __forceinline__ void hmma(float* d, const uint32_t* a, const uint32_t* b) {
    asm volatile("mma.sync.aligned.m16n8k16.row.col.f32.bf16.bf16.f32 "
        "{%0,%1,%2,%3}, {%4,%5,%6,%7}, {%8,%9}, {%0,%1,%2,%3};"
        : "+f"(d[0]), "+f"(d[1]), "+f"(d[2]), "+f"(d[3])
        : "r"(a[0]), "r"(a[1]), "r"(a[2]), "r"(a[3]), "r"(b[0]), "r"(b[1]));
}
__device__ __forceinline__ float tanh_f(float x) {
    float e = __expf(2.0f * x);
    return 1.0f - __fdividef(2.0f, e + 1.0f);
}
__device__ __forceinline__ float sig_f(float x) {
    return __fdividef(1.0f, 1.0f + __expf(-x));
}

// ------------------------- setup kernels -------------------------
__global__ void k_detect(const int* x32) {
    if (threadIdx.x == 0) {
        int f = 1;
        for (int i = 1; i < 64; i += 2)
            if (x32[i] != 0) f = 0;
        g_xflag = f;
    }
}
__global__ void k_zero() {
    int id = blockIdx.x * 256 + threadIdx.x;          // 0..131071
    uint4 z = make_uint4(0, 0, 0, 0);
    if (id < 32768)      ((uint4*)g_hA[0])[id] = z;
    else if (id < 65536) ((uint4*)g_hB[0])[id - 32768] = z;
    else                 ((uint4*)g_c)[id - 65536] = z;
}
__global__ void k_prep(const float* __restrict__ embed,
                       const float* __restrict__ Wg, const float* __restrict__ Wi,
                       const float* __restrict__ Wf, const float* __restrict__ Wo,
                       const float* __restrict__ bg, const float* __restrict__ bi,
                       const float* __restrict__ bfp, const float* __restrict__ bo) {
    int id = blockIdx.x * 256 + threadIdx.x;          // 0..40959
    int v = id >> 12, col = id & (G4H - 1);
    int u = col >> 2, gi = col & 3;
    const float* W  = (gi == 0) ? Wg : (gi == 1) ? Wi : (gi == 2) ? Wf : Wo;
    const float* bb = (gi == 0) ? bg : (gi == 1) ? bi : (gi == 2) ? bfp : bo;
    float s = bb[u];
#pragma unroll
    for (int e = 0; e < EMB; e++)
        s += embed[v * EMB + e] * W[u * EMB + e];
    g_xt[id] = s;
}
// gate-interleave + bf16 hi/lo split of recurrent weights: row 4u+gate
__global__ void k_split(const float* __restrict__ Wg, const float* __restrict__ Wi,
                        const float* __restrict__ Wf, const float* __restrict__ Wo) {
    int r = blockIdx.x, u = r >> 2, gi = r & 3;
    const float* W = (gi == 0) ? Wg : (gi == 1) ? Wi : (gi == 2) ? Wf : Wo;
    int c0 = threadIdx.x * 4;
    float4 w = *(const float4*)&W[u * HID + c0];
    float ws[4] = {w.x, w.y, w.z, w.w};
    __align__(8) __nv_bfloat16 hi[4], lo[4];
#pragma unroll
    for (int j = 0; j < 4; j++) {
        hi[j] = __float2bfloat16(ws[j]);
        lo[j] = __float2bfloat16(ws[j] - __bfloat162float(hi[j]));
    }
    *(uint2*)&g_Whi[r * HID + c0] = *(uint2*)hi;
    *(uint2*)&g_Wlo[r * HID + c0] = *(uint2*)lo;
}

// ------------------------- the timestep kernel -------------------------
// grid (32, 4): bx = N-tile (128 gate cols), by = M-tile (64 batch rows)
// 256 threads = 8 warps in a 2x4 grid; warp tile 32(M) x 32(N).
// z = hA@Whi^T + hA@Wlo^T + hB@Whi^T  (fp32 HMMA accum)
__global__ void __launch_bounds__(256, 1) k_step(const void* __restrict__ xin, int t) {
    extern __shared__ __align__(1024) char smem[];
    uint32_t sb = smem_u32(smem);
    int tid = threadIdx.x, wid = tid >> 5, lane = tid & 31;
    int n0 = blockIdx.x * 128, m0 = blockIdx.y * 64;

    const __nv_bfloat16* __restrict__ hA = g_hA[t & 1];
    const __nv_bfloat16* __restrict__ hB = g_hB[t & 1];
    __nv_bfloat16* __restrict__ hoA = g_hA[(t + 1) & 1];
    __nv_bfloat16* __restrict__ hoB = g_hB[(t + 1) & 1];

    // ---- load one K-chunk (64 k) into a stage (swizzle on 16B units) ----
    auto load_chunk = [&](int c, int s) {
        uint32_t s0 = sb + s * STG;
        int kc = c * 64;
#pragma unroll
        for (int it = 0; it < 2; it++) {
            int idx = tid + it * 256;                 // 0..511: A rows 64 x 8 chunks
            int row = idx >> 3, c16 = idx & 7;
            uint32_t off = row * 128 + ((c16 ^ (row & 7)) * 16);
            int src = (m0 + row) * HID + kc + c16 * 8;
            cp16(s0 + off,        hA + src);
            cp16(s0 + 8192 + off, hB + src);
        }
#pragma unroll
        for (int it = 0; it < 4; it++) {
            int idx = tid + it * 256;                 // 0..1023: B rows 128 x 8 chunks
            int row = idx >> 3, c16 = idx & 7;
            uint32_t off = row * 128 + ((c16 ^ (row & 7)) * 16);
            int src = (n0 + row) * HID + kc + c16 * 8;
            cp16(s0 + 16384 + off, g_Whi + src);
            cp16(s0 + 32768 + off, g_Wlo + src);
        }
    };

    int wr = wid >> 2, wc = wid & 3;                  // warp coords in 2x4
    int ar0 = 32 * wr;                                // warp A-row base (of 64)
    int bn0 = 32 * wc;                                // warp B-row base (of 128)
    float acc[2][4][4];
#pragma unroll
    for (int mt = 0; mt < 2; mt++)
#pragma unroll
        for (int nb = 0; nb < 4; nb++)
#pragma unroll
            for (int q = 0; q < 4; q++) acc[mt][nb][q] = 0.f;

    auto compute_chunk = [&](uint32_t s0) {
        uint32_t Ab[2] = {s0, s0 + 8192};
        uint32_t Bb[2] = {s0 + 16384, s0 + 32768};
#pragma unroll
        for (int term = 0; term < 3; term++) {
            uint32_t Abase = Ab[term >> 1];           // terms 0,1: Ahi; term 2: Alo
            uint32_t Bbase = Bb[term == 1 ? 1 : 0];   // term 1: Blo; else Bhi
#pragma unroll
            for (int kk = 0; kk < 64; kk += 16) {
                uint32_t a[2][4];
#pragma unroll
                for (int mt = 0; mt < 2; mt++) {
                    int r = ar0 + mt * 16 + (lane & 15);
                    int kch = (kk >> 3) + (lane >> 4);
                    ldsm4(a[mt], Abase + r * 128 + ((kch ^ (r & 7)) * 16));
                }
#pragma unroll
                for (int nb2 = 0; nb2 < 2; nb2++) {
                    uint32_t b[4];
                    int nr = bn0 + nb2 * 16 + ((lane >> 4) * 8) + (lane & 7);
                    int kch = (kk >> 3) + ((lane >> 3) & 1);
                    ldsm4(b, Bbase + nr * 128 + ((kch ^ (nr & 7)) * 16));
                    hmma(acc[0][2 * nb2],     a[0], b);
                    hmma(acc[0][2 * nb2 + 1], a[0], b + 2);
                    hmma(acc[1][2 * nb2],     a[1], b);
                    hmma(acc[1][2 * nb2 + 1], a[1], b + 2);
                }
            }
        }
    };

    load_chunk(0, 0); CP_COMMIT();
    load_chunk(1, 1); CP_COMMIT();
    for (int c = 0; c < 16; c++) {
        if (c >= 14) CP_WAIT0(); else CP_WAIT1();
        __syncthreads();
        if (c < 14) { load_chunk(c + 2, (c + 2) % 3); CP_COMMIT(); }
        compute_chunk(sb + (c % 3) * STG);
    }
    __syncthreads();

    // ---- park z in SMEM (stride 132 floats), then fused LSTM epilogue ----
    float* zs = (float*)smem;
#pragma unroll
    for (int mt = 0; mt < 2; mt++)
#pragma unroll
        for (int nb = 0; nb < 4; nb++) {
            int r = 32 * wr + mt * 16 + (lane >> 2);
            int cc = 32 * wc + nb * 8 + 2 * (lane & 3);
            *(float2*)&zs[r * 132 + cc]       = make_float2(acc[mt][nb][0], acc[mt][nb][1]);
            *(float2*)&zs[(r + 8) * 132 + cc] = make_float2(acc[mt][nb][2], acc[mt][nb][3]);
        }
    __syncthreads();

    // 256 threads: 4 threads per batch row, each handles 32 gate cols (8 units)
    int row = tid >> 2, quarter = tid & 3;
    int m = m0 + row;
    int v = g_xflag ? (int)((const long long*)xin)[m * SEQT + t]
                    : ((const int*)xin)[m * SEQT + t];
    int gcb = n0 + 32 * quarter;                      // global gate-col base
    int ub = gcb >> 2;                                // 8 hidden units per thread
    const float* zr = &zs[row * 132 + 32 * quarter];
    float cn[8];
    __align__(16) __nv_bfloat16 h8[8], l8[8];
#pragma unroll
    for (int q = 0; q < 2; q++) {
        float4 cold = *(const float4*)&g_c[m * HID + ub + 4 * q];
        float co[4] = {cold.x, cold.y, cold.z, cold.w};
#pragma unroll
        for (int jj = 0; jj < 4; jj++) {
            int j = 4 * q + jj;
            float4 z4 = *(const float4*)&zr[4 * j];
            float4 xt = *(const float4*)&g_xt[v * G4H + gcb + 4 * j];
            float gg = tanh_f(z4.x + xt.x);
            float ii = sig_f(z4.y + xt.y);
            float ff = sig_f(z4.z + xt.z);
            float oo = sig_f(z4.w + xt.w);
            float cc = gg * ii + co[jj] * ff;
            cn[j] = cc;
            float hv = tanh_f(cc) * oo;
            h8[j] = __float2bfloat16(hv);
            l8[j] = __float2bfloat16(hv - __bfloat162float(h8[j]));
        }
    }
#pragma unroll
    for (int q = 0; q < 2; q++)
        *(float4*)&g_c[m * HID + ub + 4 * q] =
            make_float4(cn[4 * q], cn[4 * q + 1], cn[4 * q + 2], cn[4 * q + 3]);
    *(uint4*)&hoA[m * HID + ub] = *(uint4*)h8;
    *(uint4*)&hoB[m * HID + ub] = *(uint4*)l8;
}

// ------------------------- final projection -------------------------
__global__ void k_out(const float* __restrict__ Wp, const float* __restrict__ bp,
                      float* __restrict__ out) {
    __shared__ float s[NCLS * 128];
    int b = blockIdx.x, tid = threadIdx.x;
    const __nv_bfloat16* hA = g_hA[0] + b * HID;      // after t=255, h lives in buf 0
    const __nv_bfloat16* hB = g_hB[0] + b * HID;
    float acc[NCLS];
#pragma unroll
    for (int c = 0; c < NCLS; c++) acc[c] = 0.f;
    for (int k = tid; k < HID; k += 128) {
        float hv = __bfloat162float(hA[k]) + __bfloat162float(hB[k]);
#pragma unroll
        for (int c = 0; c < NCLS; c++) acc[c] += hv * Wp[c * HID + k];
    }
#pragma unroll
    for (int c = 0; c < NCLS; c++) s[c * 128 + tid] = acc[c];
    __syncthreads();
    if (tid < NCLS) {
        float sum = bp[tid];
        for (int j = 0; j < 128; j++) sum += s[tid * 128 + j];
        out[b * NCLS + tid] = sum;
    }
}

// ------------------------- launch -------------------------
extern "C" void kernel_launch(void* const* d_in, const int* in_sizes, int n_in,
                              void* d_out, int out_size) {
    (void)in_sizes; (void)n_in; (void)out_size;
    const void*  x     = d_in[0];
    const float* embed = (const float*)d_in[1];
    const float* Wgx = (const float*)d_in[2],  *Wix = (const float*)d_in[3];
    const float* Wfx = (const float*)d_in[4],  *Wox = (const float*)d_in[5];
    const float* Wgh = (const float*)d_in[6],  *Wih = (const float*)d_in[7];
    const float* Wfh = (const float*)d_in[8],  *Woh = (const float*)d_in[9];
    const float* Wph = (const float*)d_in[10];
    const float* bg = (const float*)d_in[11],  *bi = (const float*)d_in[12];
    const float* bfp = (const float*)d_in[13], *bo = (const float*)d_in[14];
    const float* bp = (const float*)d_in[15];

    cudaFuncSetAttribute(k_step, cudaFuncAttributeMaxDynamicSharedMemorySize, SMEM_TOTAL);

    k_detect<<<1, 32>>>((const int*)x);
    k_zero<<<512, 256>>>();
    k_prep<<<160, 256>>>(embed, Wgx, Wix, Wfx, Wox, bg, bi, bfp, bo);
    k_split<<<4096, 256>>>(Wgh, Wih, Wfh, Woh);

    for (int t = 0; t < SEQT; t++)
        k_step<<<dim3(32, 4), 256, SMEM_TOTAL>>>(x, t);

    k_out<<<256, 128>>>(Wph, bp, (float*)d_out);
}

// round 16
// speedup vs baseline: 2.2974x; 2.2974x over previous
#include <cuda_runtime.h>
#include <cuda_fp16.h>
#include <cstdint>

#define BATCH 256
#define SEQT  256
#define HID   1024
#define G4H   4096
#define EMB   10
#define NVOC  10
#define NCLS  10

#define STG        32768                 // stage: hA 8K | hB 8K | W 16K
#define SMEM_TOTAL (3 * STG)

// Device-global scratch (allocation-free rule)
__device__ __half g_WF[G4H * HID];               // 8 MB  interleaved W (fp16)
__device__ __half g_hA[2][BATCH * HID];          // h hi (fp16), double-buffered
__device__ __half g_hB[2][BATCH * HID];          // h lo (fp16)
__device__ float g_c[BATCH * HID];
__device__ float g_xt[NVOC * G4H];
__device__ int   g_xflag;

// ------------------------- PTX helpers (baseline sm_80+ features) ----------
__device__ __forceinline__ uint32_t smem_u32(const void* p) {
    uint32_t a;
    asm("{ .reg .u64 t; cvta.to.shared.u64 t, %1; cvt.u32.u64 %0, t; }" : "=r"(a) : "l"(p));
    return a;
}
__device__ __forceinline__ void cp16(uint32_t dst, const void* src) {
    asm volatile("cp.async.cg.shared.global [%0], [%1], 16;" :: "r"(dst), "l"(src) : "memory");
}
#define CP_COMMIT() asm volatile("cp.async.commit_group;" ::: "memory")
#define CP_WAIT1()  asm volatile("cp.async.wait_group 1;" ::: "memory")
#define CP_WAIT0()  asm volatile("cp.async.wait_group 0;" ::: "memory")

__device__ __forceinline__ void ldsm4(uint32_t* r, uint32_t addr) {
    asm volatile("ldmatrix.sync.aligned.m8n8.x4.shared.b16 {%0,%1,%2,%3}, [%4];"
        : "=r"(r[0]), "=r"(r[1]), "=r"(r[2]), "=r"(r[3]) : "r"(addr));
}
__device__ __forceinline__ void hmma(float* d, const uint32_t* a, const uint32_t* b) {
    asm volatile("mma.sync.aligned.m16n8k16.row.col.f32.f16.f16.f32 "
        "{%0,%1,%2,%3}, {%4,%5,%6,%7}, {%8,%9}, {%0,%1,%2,%3};"
        : "+f"(d[0]), "+f"(d[1]), "+f"(d[2]), "+f"(d[3])
        : "r"(a[0]), "r"(a[1]), "r"(a[2]), "r"(a[3]), "r"(b[0]), "r"(b[1]));
}
__device__ __forceinline__ float tanh_f(float x) {
    float e = __expf(2.0f * x);
    return 1.0f - __fdividef(2.0f, e + 1.0f);
}
__device__ __forceinline__ float sig_f(float x) {
    return __fdividef(1.0f, 1.0f + __expf(-x));
}

// ------------------------- setup kernels -------------------------
__global__ void k_detect(const int* x32) {
    if (threadIdx.x == 0) {
        int f = 1;
        for (int i = 1; i < 64; i += 2)
            if (x32[i] != 0) f = 0;
        g_xflag = f;
    }
}
__global__ void k_zero() {
    int id = blockIdx.x * 256 + threadIdx.x;          // 0..131071
    uint4 z = make_uint4(0, 0, 0, 0);
    if (id < 32768)      ((uint4*)g_hA[0])[id] = z;   // 512 KB
    else if (id < 65536) ((uint4*)g_hB[0])[id - 32768] = z;
    else                 ((uint4*)g_c)[id - 65536] = z;
}
__global__ void k_prep(const float* __restrict__ embed,
                       const float* __restrict__ Wg, const float* __restrict__ Wi,
                       const float* __restrict__ Wf, const float* __restrict__ Wo,
                       const float* __restrict__ bg, const float* __restrict__ bi,
                       const float* __restrict__ bfp, const float* __restrict__ bo) {
    int id = blockIdx.x * 256 + threadIdx.x;          // 0..40959
    int v = id >> 12, col = id & (G4H - 1);
    int u = col >> 2, gi = col & 3;
    const float* W  = (gi == 0) ? Wg : (gi == 1) ? Wi : (gi == 2) ? Wf : Wo;
    const float* bb = (gi == 0) ? bg : (gi == 1) ? bi : (gi == 2) ? bfp : bo;
    float s = bb[u];
#pragma unroll
    for (int e = 0; e < EMB; e++)
        s += embed[v * EMB + e] * W[u * EMB + e];
    g_xt[id] = s;
}
// gate-interleave + fp16 convert of recurrent weights: row 4u+gate
__global__ void k_cvt(const float* __restrict__ Wg, const float* __restrict__ Wi,
                      const float* __restrict__ Wf, const float* __restrict__ Wo) {
    int r = blockIdx.x, u = r >> 2, gi = r & 3;
    const float* W = (gi == 0) ? Wg : (gi == 1) ? Wi : (gi == 2) ? Wf : Wo;
    int c0 = threadIdx.x * 4;
    float4 w = *(const float4*)&W[u * HID + c0];
    __align__(8) __half f[4];
    f[0] = __float2half(w.x); f[1] = __float2half(w.y);
    f[2] = __float2half(w.z); f[3] = __float2half(w.w);
    *(uint2*)&g_WF[r * HID + c0] = *(uint2*)f;
}

// ------------------------- the timestep kernel -------------------------
// grid (32, 4): bx = N-tile (128 gate cols), by = M-tile (64 batch rows)
// 128 threads = 4 warps in a 2x2 grid; warp tile 32(M) x 64(N).
// z = hA@W^T + hB@W^T  (fp32 HMMA accum; B fragments shared by both terms)
__global__ void __launch_bounds__(128, 1) k_step(const void* __restrict__ xin, int t) {
    extern __shared__ __align__(1024) char smem[];
    uint32_t sb = smem_u32(smem);
    int tid = threadIdx.x, wid = tid >> 5, lane = tid & 31;
    int n0 = blockIdx.x * 128, m0 = blockIdx.y * 64;

    const __half* __restrict__ hA = g_hA[t & 1];
    const __half* __restrict__ hB = g_hB[t & 1];
    __half* __restrict__ hoA = g_hA[(t + 1) & 1];
    __half* __restrict__ hoB = g_hB[(t + 1) & 1];

    // ---- load one K-chunk (64 k) into a stage (swizzle on 16B units) ----
    auto load_chunk = [&](int c, int s) {
        uint32_t s0 = sb + s * STG;
        int kc = c * 64;
#pragma unroll
        for (int it = 0; it < 4; it++) {
            int idx = tid + it * 128;                 // 0..511: A rows 64 x 8 chunks
            int row = idx >> 3, c16 = idx & 7;
            uint32_t off = row * 128 + ((c16 ^ (row & 7)) * 16);
            int src = (m0 + row) * HID + kc + c16 * 8;
            cp16(s0 + off,        hA + src);
            cp16(s0 + 8192 + off, hB + src);
        }
#pragma unroll
        for (int it = 0; it < 8; it++) {
            int idx = tid + it * 128;                 // 0..1023: B rows 128 x 8 chunks
            int row = idx >> 3, c16 = idx & 7;
            uint32_t off = row * 128 + ((c16 ^ (row & 7)) * 16);
            cp16(s0 + 16384 + off, g_WF + (n0 + row) * HID + kc + c16 * 8);
        }
    };

    int wr = wid >> 1, wc = wid & 1;                  // warp coords in 2x2
    int ar0 = 32 * wr;                                // warp A-row base (of 64)
    int bn0 = 64 * wc;                                // warp B-row base (of 128)
    float acc[2][8][4];
#pragma unroll
    for (int mt = 0; mt < 2; mt++)
#pragma unroll
        for (int nb = 0; nb < 8; nb++)
#pragma unroll
            for (int q = 0; q < 4; q++) acc[mt][nb][q] = 0.f;

    auto compute_chunk = [&](uint32_t s0) {
        uint32_t Bbase = s0 + 16384;
#pragma unroll
        for (int kk = 0; kk < 64; kk += 16) {
            uint32_t aA[2][4], aB[2][4], b4[4][4];
#pragma unroll
            for (int mt = 0; mt < 2; mt++) {
                int r = ar0 + mt * 16 + (lane & 15);
                int kch = (kk >> 3) + (lane >> 4);
                uint32_t off = r * 128 + ((kch ^ (r & 7)) * 16);
                ldsm4(aA[mt], s0 + off);
                ldsm4(aB[mt], s0 + 8192 + off);
            }
#pragma unroll
            for (int nb2 = 0; nb2 < 4; nb2++) {
                int nr = bn0 + nb2 * 16 + ((lane >> 4) * 8) + (lane & 7);
                int kch = (kk >> 3) + ((lane >> 3) & 1);
                ldsm4(b4[nb2], Bbase + nr * 128 + ((kch ^ (nr & 7)) * 16));
            }
            // term 1: hA @ W  (16 HMMAs, all-distinct accumulators)
#pragma unroll
            for (int nb2 = 0; nb2 < 4; nb2++) {
                hmma(acc[0][2 * nb2],     aA[0], b4[nb2]);
                hmma(acc[0][2 * nb2 + 1], aA[0], b4[nb2] + 2);
                hmma(acc[1][2 * nb2],     aA[1], b4[nb2]);
                hmma(acc[1][2 * nb2 + 1], aA[1], b4[nb2] + 2);
            }
            // term 2: hB @ W  (same accs, 16 instructions after their last write)
#pragma unroll
            for (int nb2 = 0; nb2 < 4; nb2++) {
                hmma(acc[0][2 * nb2],     aB[0], b4[nb2]);
                hmma(acc[0][2 * nb2 + 1], aB[0], b4[nb2] + 2);
                hmma(acc[1][2 * nb2],     aB[1], b4[nb2]);
                hmma(acc[1][2 * nb2 + 1], aB[1], b4[nb2] + 2);
            }
        }
    };

    load_chunk(0, 0); CP_COMMIT();
    load_chunk(1, 1); CP_COMMIT();
    for (int c = 0; c < 16; c++) {
        if (c >= 14) CP_WAIT0(); else CP_WAIT1();
        __syncthreads();
        if (c < 14) { load_chunk(c + 2, (c + 2) % 3); CP_COMMIT(); }
        compute_chunk(sb + (c % 3) * STG);
    }
    __syncthreads();

    // ---- park z in SMEM (stride 132 floats), then fused LSTM epilogue ----
    float* zs = (float*)smem;
#pragma unroll
    for (int mt = 0; mt < 2; mt++)
#pragma unroll
        for (int nb = 0; nb < 8; nb++) {
            int r = 32 * wr + mt * 16 + (lane >> 2);
            int cc = 64 * wc + nb * 8 + 2 * (lane & 3);
            *(float2*)&zs[r * 132 + cc]       = make_float2(acc[mt][nb][0], acc[mt][nb][1]);
            *(float2*)&zs[(r + 8) * 132 + cc] = make_float2(acc[mt][nb][2], acc[mt][nb][3]);
        }
    __syncthreads();

    // 128 threads: 2 per batch row, each handles 64 gate cols (16 units)
    int row = tid >> 1, half = tid & 1;
    int m = m0 + row;
    int v = g_xflag ? (int)((const long long*)xin)[m * SEQT + t]
                    : ((const int*)xin)[m * SEQT + t];
    int gcb = n0 + 64 * half;                         // global gate-col base
    int ub = gcb >> 2;                                // 16 hidden units per thread
    const float* zr = &zs[row * 132 + 64 * half];
    float cn[16];
    __align__(16) __half h16[16], l16[16];
#pragma unroll
    for (int q = 0; q < 4; q++) {
        float4 cold = *(const float4*)&g_c[m * HID + ub + 4 * q];
        float co[4] = {cold.x, cold.y, cold.z, cold.w};
#pragma unroll
        for (int jj = 0; jj < 4; jj++) {
            int j = 4 * q + jj;
            float4 z4 = *(const float4*)&zr[4 * j];
            float4 xt = *(const float4*)&g_xt[v * G4H + gcb + 4 * j];
            float gg = tanh_f(z4.x + xt.x);
            float ii = sig_f(z4.y + xt.y);
            float ff = sig_f(z4.z + xt.z);
            float oo = sig_f(z4.w + xt.w);
            float cc = gg * ii + co[jj] * ff;
            cn[j] = cc;
            float hv = tanh_f(cc) * oo;
            h16[j] = __float2half(hv);
            l16[j] = __float2half(hv - __half2float(h16[j]));
        }
    }
#pragma unroll
    for (int q = 0; q < 4; q++)
        *(float4*)&g_c[m * HID + ub + 4 * q] =
            make_float4(cn[4 * q], cn[4 * q + 1], cn[4 * q + 2], cn[4 * q + 3]);
    *(uint4*)&hoA[m * HID + ub]     = ((uint4*)h16)[0];
    *(uint4*)&hoA[m * HID + ub + 8] = ((uint4*)h16)[1];
    *(uint4*)&hoB[m * HID + ub]     = ((uint4*)l16)[0];
    *(uint4*)&hoB[m * HID + ub + 8] = ((uint4*)l16)[1];
}

// ------------------------- final projection -------------------------
__global__ void k_out(const float* __restrict__ Wp, const float* __restrict__ bp,
                      float* __restrict__ out) {
    __shared__ float s[NCLS * 128];
    int b = blockIdx.x, tid = threadIdx.x;
    const __half* hA = g_hA[0] + b * HID;             // after t=255, h lives in buf 0
    const __half* hB = g_hB[0] + b * HID;
    float acc[NCLS];
#pragma unroll
    for (int c = 0; c < NCLS; c++) acc[c] = 0.f;
    for (int k = tid; k < HID; k += 128) {
        float hv = __half2float(hA[k]) + __half2float(hB[k]);
#pragma unroll
        for (int c = 0; c < NCLS; c++) acc[c] += hv * Wp[c * HID + k];
    }
#pragma unroll
    for (int c = 0; c < NCLS; c++) s[c * 128 + tid] = acc[c];
    __syncthreads();
    if (tid < NCLS) {
        float sum = bp[tid];
        for (int j = 0; j < 128; j++) sum += s[tid * 128 + j];
        out[b * NCLS + tid] = sum;
    }
}

// ------------------------- launch -------------------------
extern "C" void kernel_launch(void* const* d_in, const int* in_sizes, int n_in,
                              void* d_out, int out_size) {
    (void)in_sizes; (void)n_in; (void)out_size;
    const void*  x     = d_in[0];
    const float* embed = (const float*)d_in[1];
    const float* Wgx = (const float*)d_in[2],  *Wix = (const float*)d_in[3];
    const float* Wfx = (const float*)d_in[4],  *Wox = (const float*)d_in[5];
    const float* Wgh = (const float*)d_in[6],  *Wih = (const float*)d_in[7];
    const float* Wfh = (const float*)d_in[8],  *Woh = (const float*)d_in[9];
    const float* Wph = (const float*)d_in[10];
    const float* bg = (const float*)d_in[11],  *bi = (const float*)d_in[12];
    const float* bfp = (const float*)d_in[13], *bo = (const float*)d_in[14];
    const float* bp = (const float*)d_in[15];

    cudaFuncSetAttribute(k_step, cudaFuncAttributeMaxDynamicSharedMemorySize, SMEM_TOTAL);

    k_detect<<<1, 32>>>((const int*)x);
    k_zero<<<512, 256>>>();
    k_prep<<<160, 256>>>(embed, Wgx, Wix, Wfx, Wox, bg, bi, bfp, bo);
    k_cvt<<<4096, 256>>>(Wgh, Wih, Wfh, Woh);

    for (int t = 0; t < SEQT; t++)
        k_step<<<dim3(32, 4), 128, SMEM_TOTAL>>>(x, t);

    k_out<<<256, 128>>>(Wph, bp, (float*)d_out);
}

// round 17
// speedup vs baseline: 3.0862x; 1.3433x over previous
#include <cuda_runtime.h>
#include <cuda_fp16.h>
#include <cstdint>

#define BATCH 256
#define SEQT  256
#define HID   1024
#define G4H   4096
#define EMB   10
#define NVOC  10
#define NCLS  10

#define STG        24576                 // stage: h 8K | W 16K
#define SMEM_TOTAL (3 * STG)

// Device-global scratch (allocation-free rule)
__device__ __half g_WF[G4H * HID];               // 8 MB  interleaved W (fp16)
__device__ __half g_h[2][BATCH * HID];           // h (fp16), double-buffered
__device__ float g_c[BATCH * HID];
__device__ float g_xt[NVOC * G4H];
__device__ int   g_xflag;

// ------------------------- PTX helpers (baseline sm_80+ features) ----------
__device__ __forceinline__ uint32_t smem_u32(const void* p) {
    uint32_t a;
    asm("{ .reg .u64 t; cvta.to.shared.u64 t, %1; cvt.u32.u64 %0, t; }" : "=r"(a) : "l"(p));
    return a;
}
__device__ __forceinline__ void cp16(uint32_t dst, const void* src) {
    asm volatile("cp.async.cg.shared.global [%0], [%1], 16;" :: "r"(dst), "l"(src) : "memory");
}
#define CP_COMMIT() asm volatile("cp.async.commit_group;" ::: "memory")
#define CP_WAIT1()  asm volatile("cp.async.wait_group 1;" ::: "memory")
#define CP_WAIT0()  asm volatile("cp.async.wait_group 0;" ::: "memory")

__device__ __forceinline__ void ldsm4(uint32_t* r, uint32_t addr) {
    asm volatile("ldmatrix.sync.aligned.m8n8.x4.shared.b16 {%0,%1,%2,%3}, [%4];"
        : "=r"(r[0]), "=r"(r[1]), "=r"(r[2]), "=r"(r[3]) : "r"(addr));
}
__device__ __forceinline__ void hmma(float* d, const uint32_t* a, const uint32_t* b) {
    asm volatile("mma.sync.aligned.m16n8k16.row.col.f32.f16.f16.f32 "
        "{%0,%1,%2,%3}, {%4,%5,%6,%7}, {%8,%9}, {%0,%1,%2,%3};"
        : "+f"(d[0]), "+f"(d[1]), "+f"(d[2]), "+f"(d[3])
        : "r"(a[0]), "r"(a[1]), "r"(a[2]), "r"(a[3]), "r"(b[0]), "r"(b[1]));
}
__device__ __forceinline__ float tanh_f(float x) {
    float e = __expf(2.0f * x);
    return 1.0f - __fdividef(2.0f, e + 1.0f);
}
__device__ __forceinline__ float sig_f(float x) {
    return __fdividef(1.0f, 1.0f + __expf(-x));
}

// ------------------------- setup kernels -------------------------
__global__ void k_detect(const int* x32) {
    if (threadIdx.x == 0) {
        int f = 1;
        for (int i = 1; i < 64; i += 2)
            if (x32[i] != 0) f = 0;
        g_xflag = f;
    }
}
__global__ void k_zero() {
    int id = blockIdx.x * 256 + threadIdx.x;          // 0..98303
    uint4 z = make_uint4(0, 0, 0, 0);
    if (id < 32768) ((uint4*)g_h[0])[id] = z;         // 512 KB
    else            ((uint4*)g_c)[id - 32768] = z;    // 1 MB
}
__global__ void k_prep(const float* __restrict__ embed,
                       const float* __restrict__ Wg, const float* __restrict__ Wi,
                       const float* __restrict__ Wf, const float* __restrict__ Wo,
                       const float* __restrict__ bg, const float* __restrict__ bi,
                       const float* __restrict__ bfp, const float* __restrict__ bo) {
    int id = blockIdx.x * 256 + threadIdx.x;          // 0..40959
    int v = id >> 12, col = id & (G4H - 1);
    int u = col >> 2, gi = col & 3;
    const float* W  = (gi == 0) ? Wg : (gi == 1) ? Wi : (gi == 2) ? Wf : Wo;
    const float* bb = (gi == 0) ? bg : (gi == 1) ? bi : (gi == 2) ? bfp : bo;
    float s = bb[u];
#pragma unroll
    for (int e = 0; e < EMB; e++)
        s += embed[v * EMB + e] * W[u * EMB + e];
    g_xt[id] = s;
}
// gate-interleave + fp16 convert of recurrent weights: row 4u+gate
__global__ void k_cvt(const float* __restrict__ Wg, const float* __restrict__ Wi,
                      const float* __restrict__ Wf, const float* __restrict__ Wo) {
    int r = blockIdx.x, u = r >> 2, gi = r & 3;
    const float* W = (gi == 0) ? Wg : (gi == 1) ? Wi : (gi == 2) ? Wf : Wo;
    int c0 = threadIdx.x * 4;
    float4 w = *(const float4*)&W[u * HID + c0];
    __align__(8) __half f[4];
    f[0] = __float2half(w.x); f[1] = __float2half(w.y);
    f[2] = __float2half(w.z); f[3] = __float2half(w.w);
    *(uint2*)&g_WF[r * HID + c0] = *(uint2*)f;
}

// ------------------------- the timestep kernel -------------------------
// grid (32, 4): bx = N-tile (128 gate cols), by = M-tile (64 batch rows)
// 128 threads = 4 warps in a 2x2 grid; warp tile 32(M) x 64(N).
// z = h@W^T  (fp32 HMMA accum), single fp16 term.
__global__ void __launch_bounds__(128, 1) k_step(const void* __restrict__ xin, int t) {
    extern __shared__ __align__(1024) char smem[];
    uint32_t sb = smem_u32(smem);
    int tid = threadIdx.x, wid = tid >> 5, lane = tid & 31;
    int n0 = blockIdx.x * 128, m0 = blockIdx.y * 64;

    const __half* __restrict__ hin = g_h[t & 1];
    __half* __restrict__ hout = g_h[(t + 1) & 1];

    // ---- load one K-chunk (64 k) into a stage (swizzle on 16B units) ----
    auto load_chunk = [&](int c, int s) {
        uint32_t s0 = sb + s * STG;
        int kc = c * 64;
#pragma unroll
        for (int it = 0; it < 4; it++) {
            int idx = tid + it * 128;                 // 0..511: A rows 64 x 8 chunks
            int row = idx >> 3, c16 = idx & 7;
            uint32_t off = row * 128 + ((c16 ^ (row & 7)) * 16);
            cp16(s0 + off, hin + (m0 + row) * HID + kc + c16 * 8);
        }
#pragma unroll
        for (int it = 0; it < 8; it++) {
            int idx = tid + it * 128;                 // 0..1023: B rows 128 x 8 chunks
            int row = idx >> 3, c16 = idx & 7;
            uint32_t off = row * 128 + ((c16 ^ (row & 7)) * 16);
            cp16(s0 + 8192 + off, g_WF + (n0 + row) * HID + kc + c16 * 8);
        }
    };

    int wr = wid >> 1, wc = wid & 1;                  // warp coords in 2x2
    int ar0 = 32 * wr;                                // warp A-row base (of 64)
    int bn0 = 64 * wc;                                // warp B-row base (of 128)
    float acc[2][8][4];
#pragma unroll
    for (int mt = 0; mt < 2; mt++)
#pragma unroll
        for (int nb = 0; nb < 8; nb++)
#pragma unroll
            for (int q = 0; q < 4; q++) acc[mt][nb][q] = 0.f;

    auto compute_chunk = [&](uint32_t s0) {
        uint32_t Bbase = s0 + 8192;
#pragma unroll
        for (int kk = 0; kk < 64; kk += 16) {
            uint32_t a[2][4], b4[4][4];
#pragma unroll
            for (int mt = 0; mt < 2; mt++) {
                int r = ar0 + mt * 16 + (lane & 15);
                int kch = (kk >> 3) + (lane >> 4);
                ldsm4(a[mt], s0 + r * 128 + ((kch ^ (r & 7)) * 16));
            }
#pragma unroll
            for (int nb2 = 0; nb2 < 4; nb2++) {
                int nr = bn0 + nb2 * 16 + ((lane >> 4) * 8) + (lane & 7);
                int kch = (kk >> 3) + ((lane >> 3) & 1);
                ldsm4(b4[nb2], Bbase + nr * 128 + ((kch ^ (nr & 7)) * 16));
            }
            // 16 HMMAs, all-distinct accumulators (RAW distance = 16)
#pragma unroll
            for (int nb2 = 0; nb2 < 4; nb2++) {
                hmma(acc[0][2 * nb2],     a[0], b4[nb2]);
                hmma(acc[0][2 * nb2 + 1], a[0], b4[nb2] + 2);
                hmma(acc[1][2 * nb2],     a[1], b4[nb2]);
                hmma(acc[1][2 * nb2 + 1], a[1], b4[nb2] + 2);
            }
        }
    };

    load_chunk(0, 0); CP_COMMIT();
    load_chunk(1, 1); CP_COMMIT();
    for (int c = 0; c < 16; c++) {
        if (c >= 14) CP_WAIT0(); else CP_WAIT1();
        __syncthreads();
        if (c < 14) { load_chunk(c + 2, (c + 2) % 3); CP_COMMIT(); }
        compute_chunk(sb + (c % 3) * STG);
    }
    __syncthreads();

    // ---- park z in SMEM (stride 132 floats), then fused LSTM epilogue ----
    float* zs = (float*)smem;
#pragma unroll
    for (int mt = 0; mt < 2; mt++)
#pragma unroll
        for (int nb = 0; nb < 8; nb++) {
            int r = 32 * wr + mt * 16 + (lane >> 2);
            int cc = 64 * wc + nb * 8 + 2 * (lane & 3);
            *(float2*)&zs[r * 132 + cc]       = make_float2(acc[mt][nb][0], acc[mt][nb][1]);
            *(float2*)&zs[(r + 8) * 132 + cc] = make_float2(acc[mt][nb][2], acc[mt][nb][3]);
        }
    __syncthreads();

    // 128 threads: 2 per batch row, each handles 64 gate cols (16 units)
    int row = tid >> 1, half = tid & 1;
    int m = m0 + row;
    int v = g_xflag ? (int)((const long long*)xin)[m * SEQT + t]
                    : ((const int*)xin)[m * SEQT + t];
    int gcb = n0 + 64 * half;                         // global gate-col base
    int ub = gcb >> 2;                                // 16 hidden units per thread
    const float* zr = &zs[row * 132 + 64 * half];
    float cn[16];
    __align__(16) __half h16[16];
#pragma unroll
    for (int q = 0; q < 4; q++) {
        float4 cold = *(const float4*)&g_c[m * HID + ub + 4 * q];
        float co[4] = {cold.x, cold.y, cold.z, cold.w};
#pragma unroll
        for (int jj = 0; jj < 4; jj++) {
            int j = 4 * q + jj;
            float4 z4 = *(const float4*)&zr[4 * j];
            float4 xt = *(const float4*)&g_xt[v * G4H + gcb + 4 * j];
            float gg = tanh_f(z4.x + xt.x);
            float ii = sig_f(z4.y + xt.y);
            float ff = sig_f(z4.z + xt.z);
            float oo = sig_f(z4.w + xt.w);
            float cc = gg * ii + co[jj] * ff;
            cn[j] = cc;
            h16[j] = __float2half(tanh_f(cc) * oo);
        }
    }
#pragma unroll
    for (int q = 0; q < 4; q++)
        *(float4*)&g_c[m * HID + ub + 4 * q] =
            make_float4(cn[4 * q], cn[4 * q + 1], cn[4 * q + 2], cn[4 * q + 3]);
    *(uint4*)&hout[m * HID + ub]     = ((uint4*)h16)[0];
    *(uint4*)&hout[m * HID + ub + 8] = ((uint4*)h16)[1];
}

// ------------------------- final projection -------------------------
__global__ void k_out(const float* __restrict__ Wp, const float* __restrict__ bp,
                      float* __restrict__ out) {
    __shared__ float s[NCLS * 128];
    int b = blockIdx.x, tid = threadIdx.x;
    const __half* h = g_h[0] + b * HID;               // after t=255, h lives in buf 0
    float acc[NCLS];
#pragma unroll
    for (int c = 0; c < NCLS; c++) acc[c] = 0.f;
    for (int k = tid; k < HID; k += 128) {
        float hv = __half2float(h[k]);
#pragma unroll
        for (int c = 0; c < NCLS; c++) acc[c] += hv * Wp[c * HID + k];
    }
#pragma unroll
    for (int c = 0; c < NCLS; c++) s[c * 128 + tid] = acc[c];
    __syncthreads();
    if (tid < NCLS) {
        float sum = bp[tid];
        for (int j = 0; j < 128; j++) sum += s[tid * 128 + j];
        out[b * NCLS + tid] = sum;
    }
}

// ------------------------- launch -------------------------
extern "C" void kernel_launch(void* const* d_in, const int* in_sizes, int n_in,
                              void* d_out, int out_size) {
    (void)in_sizes; (void)n_in; (void)out_size;
    const void*  x     = d_in[0];
    const float* embed = (const float*)d_in[1];
    const float* Wgx = (const float*)d_in[2],  *Wix = (const float*)d_in[3];
    const float* Wfx = (const float*)d_in[4],  *Wox = (const float*)d_in[5];
    const float* Wgh = (const float*)d_in[6],  *Wih = (const float*)d_in[7];
    const float* Wfh = (const float*)d_in[8],  *Woh = (const float*)d_in[9];
    const float* Wph = (const float*)d_in[10];
    const float* bg = (const float*)d_in[11],  *bi = (const float*)d_in[12];
    const float* bfp = (const float*)d_in[13], *bo = (const float*)d_in[14];
    const float* bp = (const float*)d_in[15];

    cudaFuncSetAttribute(k_step, cudaFuncAttributeMaxDynamicSharedMemorySize, SMEM_TOTAL);

    k_detect<<<1, 32>>>((const int*)x);
    k_zero<<<384, 256>>>();
    k_prep<<<160, 256>>>(embed, Wgx, Wix, Wfx, Wox, bg, bi, bfp, bo);
    k_cvt<<<4096, 256>>>(Wgh, Wih, Wfh, Woh);

    for (int t = 0; t < SEQT; t++)
        k_step<<<dim3(32, 4), 128, SMEM_TOTAL>>>(x, t);

    k_out<<<256, 128>>>(Wph, bp, (float*)d_out);
}